// round 2
// baseline (speedup 1.0000x reference)
#include <cuda_runtime.h>
#include <math.h>

#define B_N 4096
#define D_N 16384

// W_FIRST = 2 - 10 * (2/49), W_LAST = 2 - W_FIRST, batch_step = (W_FIRST-W_LAST)/(B-1)
#define EPOCH_STEP (2.0 / 49.0)
#define W_FIRST_D  (2.0 - 10.0 * EPOCH_STEP)   /* ~1.5918367346938775 */
#define W_LAST_D   (2.0 - W_FIRST_D)
#define BATCH_STEP_D ((W_FIRST_D - W_LAST_D) / (double)(B_N - 1))

// ---------------------------------------------------------------------------
// Kernel 1: difficulty[i] = 0.5*loss[i] + 0.5*||gradients[i,:]||_2
// One block per row. 256 threads, float4 loads (16 iters/thread).
// Also zero-initializes out[0] (the weighted-loss accumulator) from block 0.
// ---------------------------------------------------------------------------
__global__ __launch_bounds__(256) void difficulty_kernel(
    const float* __restrict__ loss,
    const float4* __restrict__ grad,       // [B, D/4]
    float* __restrict__ out)               // out[0]=acc, out[1..B]=difficulty
{
    const int row = blockIdx.x;
    const int tid = threadIdx.x;

    if (row == 0 && tid == 0) out[0] = 0.0f;   // reset accumulator (graph replay safe)

    const float4* __restrict__ g = grad + (size_t)row * (D_N / 4);

    float s = 0.0f;
#pragma unroll 4
    for (int c = tid; c < D_N / 4; c += 256) {
        float4 v = g[c];
        s = fmaf(v.x, v.x, s);
        s = fmaf(v.y, v.y, s);
        s = fmaf(v.z, v.z, s);
        s = fmaf(v.w, v.w, s);
    }

    // warp reduce
#pragma unroll
    for (int off = 16; off > 0; off >>= 1)
        s += __shfl_xor_sync(0xFFFFFFFFu, s, off);

    __shared__ float warp_sums[8];
    if ((tid & 31) == 0) warp_sums[tid >> 5] = s;
    __syncthreads();

    if (tid == 0) {
        float tot = 0.0f;
#pragma unroll
        for (int w = 0; w < 8; w++) tot += warp_sums[w];
        out[1 + row] = 0.5f * loss[row] + 0.5f * sqrtf(tot);
    }
}

// ---------------------------------------------------------------------------
// Kernel 2: counting rank + weighted loss accumulation.
// One block per sample i; 128 threads scan all B difficulties.
// rank(i) = #{ d[j] < d[i] } + #{ d[j] == d[i] && j < i }   (stable argsort)
// weight(i) = W_FIRST - batch_step * rank(i)
// atomicAdd( out[0], loss[i]*weight(i)/B )
// ---------------------------------------------------------------------------
__global__ __launch_bounds__(128) void rank_weight_kernel(
    const float* __restrict__ loss,
    float* __restrict__ out)               // out[0]=acc, out[1..B]=difficulty
{
    const int i   = blockIdx.x;
    const int tid = threadIdx.x;
    const float* __restrict__ diff = out + 1;

    const float di = __ldg(&diff[i]);

    int cnt = 0;
#pragma unroll 4
    for (int j = tid; j < B_N; j += 128) {
        float dj = __ldg(&diff[j]);
        cnt += (dj < di) | ((dj == di) & (j < i));
    }

    // warp reduce
#pragma unroll
    for (int off = 16; off > 0; off >>= 1)
        cnt += __shfl_xor_sync(0xFFFFFFFFu, cnt, off);

    __shared__ int warp_cnt[4];
    if ((tid & 31) == 0) warp_cnt[tid >> 5] = cnt;
    __syncthreads();

    if (tid == 0) {
        int rank = warp_cnt[0] + warp_cnt[1] + warp_cnt[2] + warp_cnt[3];
        float w = (float)(W_FIRST_D - BATCH_STEP_D * (double)rank);
        float contrib = __ldg(&loss[i]) * w * (1.0f / (float)B_N);
        atomicAdd(&out[0], contrib);
    }
}

// ---------------------------------------------------------------------------
extern "C" void kernel_launch(void* const* d_in, const int* in_sizes, int n_in,
                              void* d_out, int out_size)
{
    const float*  loss = (const float*)d_in[0];
    const float4* grad = (const float4*)d_in[1];
    float* out = (float*)d_out;

    difficulty_kernel<<<B_N, 256>>>(loss, grad, out);
    rank_weight_kernel<<<B_N, 128>>>(loss, out);
}

// round 3
// speedup vs baseline: 1.0975x; 1.0975x over previous
#include <cuda_runtime.h>
#include <math.h>
#include <stdint.h>

#define B_N 4096
#define D_N 16384

// W_FIRST = 2 - 10 * (2/49), W_LAST = 2 - W_FIRST, batch_step = (W_FIRST-W_LAST)/(B-1)
#define EPOCH_STEP (2.0 / 49.0)
#define W_FIRST_D  (2.0 - 10.0 * EPOCH_STEP)   /* ~1.5918367346938775 */
#define W_LAST_D   (2.0 - W_FIRST_D)
#define BATCH_STEP_D ((W_FIRST_D - W_LAST_D) / (double)(B_N - 1))

// Sortable keys: (float_bits << 12) | row_index.
// difficulty > 0 always (0.5*loss + 0.5*||g|| with ||g|| > 0), so the raw IEEE
// bit pattern is order-preserving. Low 12 bits = index -> exact stable-argsort
// tie-break with a single u64 '<' comparison.
__device__ __align__(16) unsigned long long g_keys[B_N];

// ---------------------------------------------------------------------------
// Kernel 1: difficulty[i] = 0.5*loss[i] + 0.5*||gradients[i,:]||_2
// One block per row, 256 threads, fully unrolled float4 loads (16 in flight).
// Writes difficulty to out[1+i] AND the sortable key to g_keys[i].
// Block 0 zeroes the weighted-loss accumulator out[0].
// ---------------------------------------------------------------------------
__global__ __launch_bounds__(256) void difficulty_kernel(
    const float* __restrict__ loss,
    const float4* __restrict__ grad,       // [B, D/4]
    float* __restrict__ out)               // out[0]=acc, out[1..B]=difficulty
{
    const int row = blockIdx.x;
    const int tid = threadIdx.x;

    if (row == 0 && tid == 0) out[0] = 0.0f;   // reset accumulator (graph replay safe)

    const float4* __restrict__ g = grad + (size_t)row * (D_N / 4);

    float s = 0.0f;
#pragma unroll
    for (int it = 0; it < 16; it++) {          // 16 independent LDG.128 in flight
        float4 v = g[tid + it * 256];
        s = fmaf(v.x, v.x, s);
        s = fmaf(v.y, v.y, s);
        s = fmaf(v.z, v.z, s);
        s = fmaf(v.w, v.w, s);
    }

    // warp reduce
#pragma unroll
    for (int off = 16; off > 0; off >>= 1)
        s += __shfl_xor_sync(0xFFFFFFFFu, s, off);

    __shared__ float warp_sums[8];
    if ((tid & 31) == 0) warp_sums[tid >> 5] = s;
    __syncthreads();

    if (tid == 0) {
        float tot = 0.0f;
#pragma unroll
        for (int w = 0; w < 8; w++) tot += warp_sums[w];
        float d = 0.5f * loss[row] + 0.5f * sqrtf(tot);
        out[1 + row] = d;
        g_keys[row] = ((unsigned long long)__float_as_uint(d) << 12) | (unsigned)row;
    }
}

// ---------------------------------------------------------------------------
// Kernel 2: counting rank + weighted loss accumulation.
// Each block owns 4 consecutive i's; 128 threads scan all B keys as uint4
// (2 u64 keys per 16B load), each load reused for 4 i-compares.
// rank(i) = #{ key_j < key_i }  (exact stable-argsort rank via packed index)
// weight(i) = W_FIRST - batch_step * rank(i)
// One atomicAdd per block into out[0].
// ---------------------------------------------------------------------------
#define IPB 4   // i's per block

__global__ __launch_bounds__(128) void rank_weight_kernel(
    const float* __restrict__ loss,
    float* __restrict__ out)
{
    const int i0  = blockIdx.x * IPB;
    const int tid = threadIdx.x;

    unsigned long long ki[IPB];
#pragma unroll
    for (int k = 0; k < IPB; k++) ki[k] = g_keys[i0 + k];

    int cnt[IPB] = {0, 0, 0, 0};

    const uint4* __restrict__ keys4 = (const uint4*)g_keys;  // 2 keys per uint4

#pragma unroll 4
    for (int p = tid; p < B_N / 2; p += 128) {
        uint4 v = keys4[p];
        unsigned long long k0 = ((unsigned long long)v.y << 32) | v.x;
        unsigned long long k1 = ((unsigned long long)v.w << 32) | v.z;
#pragma unroll
        for (int k = 0; k < IPB; k++) {
            cnt[k] += (k0 < ki[k]);
            cnt[k] += (k1 < ki[k]);
        }
    }

    // warp reduce all 4 counters
#pragma unroll
    for (int off = 16; off > 0; off >>= 1) {
#pragma unroll
        for (int k = 0; k < IPB; k++)
            cnt[k] += __shfl_xor_sync(0xFFFFFFFFu, cnt[k], off);
    }

    __shared__ int warp_cnt[4][IPB];
    if ((tid & 31) == 0) {
#pragma unroll
        for (int k = 0; k < IPB; k++)
            warp_cnt[tid >> 5][k] = cnt[k];
    }
    __syncthreads();

    if (tid == 0) {
        float contrib = 0.0f;
#pragma unroll
        for (int k = 0; k < IPB; k++) {
            int rank = warp_cnt[0][k] + warp_cnt[1][k] + warp_cnt[2][k] + warp_cnt[3][k];
            float w = (float)(W_FIRST_D - BATCH_STEP_D * (double)rank);
            contrib += __ldg(&loss[i0 + k]) * w;
        }
        atomicAdd(&out[0], contrib * (1.0f / (float)B_N));
    }
}

// ---------------------------------------------------------------------------
extern "C" void kernel_launch(void* const* d_in, const int* in_sizes, int n_in,
                              void* d_out, int out_size)
{
    const float*  loss = (const float*)d_in[0];
    const float4* grad = (const float4*)d_in[1];
    float* out = (float*)d_out;

    difficulty_kernel<<<B_N, 256>>>(loss, grad, out);
    rank_weight_kernel<<<B_N / IPB, 128>>>(loss, out);
}